// round 4
// baseline (speedup 1.0000x reference)
#include <cuda_runtime.h>
#include <math.h>
#include <float.h>

#define BB   16
#define NN   4096
#define KK   4096
#define IN1  16384
#define H1   1024
#define H2   512
#define OUTD 256

// spatial grid
#define G      32
#define NCELLS (G*G*G)
#define GL     1.6f
#define GH     0.1f
#define GINVH  10.0f
#define EPSG   1e-3f

typedef unsigned long long ull;

#define FMA2(out, a, b, c) asm("fma.rn.f32x2 %0, %1, %2, %3;" : "=l"(out) : "l"(a), "l"(b), "l"(c))

__device__ __forceinline__ ull pk2(float lo, float hi) {
    ull r; asm("mov.b64 %0, {%1, %2};" : "=l"(r) : "f"(lo), "f"(hi)); return r;
}
__device__ __forceinline__ void upk2(float& lo, float& hi, ull v) {
    asm("mov.b64 {%0, %1}, %2;" : "=f"(lo), "=f"(hi) : "l"(v));
}

// ---- scratch ----
__device__ int    g_count [BB * NCELLS];
__device__ int    g_start [BB * (NCELLS + 1)];
__device__ int    g_cursor[BB * NCELLS];
__device__ int    g_pcell [BB * NN];
__device__ float4 g_sorted[BB * NN];
__device__ float  g_part1[32 * BB * H1];
__device__ float  g_part2[16 * BB * H2];
__device__ float  g_part3[16 * BB * OUTD];

__device__ __forceinline__ int cell_of(float x, float y, float z) {
    int xi = min(G - 1, max(0, (int)floorf((x + GL) * GINVH)));
    int yi = min(G - 1, max(0, (int)floorf((y + GL) * GINVH)));
    int zi = min(G - 1, max(0, (int)floorf((z + GL) * GINVH)));
    return (zi * G + yi) * G + xi;
}

// ---- binning: count ----
__global__ void k_count(const float* __restrict__ pc) {
    const int t = blockIdx.x * 256 + threadIdx.x;       // over BB*NN
    const int b = t >> 12;
    const float* p = pc + (size_t)t * 3;
    const int c = cell_of(p[0], p[1], p[2]);
    g_pcell[t] = c;
    atomicAdd(&g_count[b * NCELLS + c], 1);
}

// ---- binning: per-batch exclusive scan of 32768 cells ----
__global__ void k_scan() {
    __shared__ int warpsum[32];
    const int b = blockIdx.x;
    const int t = threadIdx.x;
    const int lane = t & 31, w = t >> 5;

    int local[32];
    int s = 0;
    const int base = b * NCELLS + t * 32;
    #pragma unroll
    for (int i = 0; i < 32; i++) { local[i] = g_count[base + i]; s += local[i]; }

    int v = s;
    #pragma unroll
    for (int off = 1; off < 32; off <<= 1) {
        int u = __shfl_up_sync(0xffffffffu, v, off);
        if (lane >= off) v += u;
    }
    if (lane == 31) warpsum[w] = v;
    __syncthreads();
    if (w == 0) {
        int ws = warpsum[lane];
        int vv = ws;
        #pragma unroll
        for (int off = 1; off < 32; off <<= 1) {
            int u = __shfl_up_sync(0xffffffffu, vv, off);
            if (lane >= off) vv += u;
        }
        warpsum[lane] = vv - ws;     // exclusive
    }
    __syncthreads();

    int run = warpsum[w] + (v - s);
    const int sb = b * (NCELLS + 1);
    #pragma unroll
    for (int i = 0; i < 32; i++) {
        g_start [sb + t * 32 + i] = run;
        g_cursor[b * NCELLS + t * 32 + i] = run;
        run += local[i];
    }
    if (t == 1023) g_start[sb + NCELLS] = run;   // == NN
}

// ---- binning: scatter ----
__global__ void k_scatter(const float* __restrict__ pc) {
    const int t = blockIdx.x * 256 + threadIdx.x;
    const int b = t >> 12;
    const float* p = pc + (size_t)t * 3;
    const int c = g_pcell[t];
    const int pos = atomicAdd(&g_cursor[b * NCELLS + c], 1);
    g_sorted[b * NN + pos] = make_float4(p[0], p[1], p[2],
                                         __int_as_float(t & (NN - 1)));
}

// ---- query: exact NN via expanding shells; writes bps row ----
__global__ void k_query(const float* __restrict__ pc,
                        const float* __restrict__ basis,
                        float* __restrict__ out_bps) {
    const int t = blockIdx.x * 256 + threadIdx.x;       // over BB*KK
    const int b = t >> 12;
    const int k = t & (KK - 1);

    const float bx = basis[k * 3 + 0];
    const float by = basis[k * 3 + 1];
    const float bz = basis[k * 3 + 2];
    const float bn = __fadd_rn(__fadd_rn(__fmul_rn(bx, bx), __fmul_rn(by, by)),
                               __fmul_rn(bz, bz));

    const int cx = min(G - 1, max(0, (int)floorf((bx + GL) * GINVH)));
    const int cy = min(G - 1, max(0, (int)floorf((by + GL) * GINVH)));
    const int cz = min(G - 1, max(0, (int)floorf((bz + GL) * GINVH)));

    const int sb = b * (NCELLS + 1);
    const float4* __restrict__ pts = g_sorted + b * NN;

    float best = FLT_MAX;
    int   bi   = 0x7fffffff;

    for (int r = 0; r < G; r++) {
        if (r >= 2) {
            float lb = (float)(r - 1) * GH;
            if (lb * lb > best + EPSG) break;
        }
        const int z0 = max(0, cz - r), z1 = min(G - 1, cz + r);
        const int y0 = max(0, cy - r), y1 = min(G - 1, cy + r);
        const int x0 = max(0, cx - r), x1 = min(G - 1, cx + r);
        for (int zz = z0; zz <= z1; zz++) {
            const bool zface = (zz == cz - r) || (zz == cz + r);
            for (int yy = y0; yy <= y1; yy++) {
                const bool yface = (yy == cy - r) || (yy == cy + r);
                int xa, xb_, nx;
                if (zface || yface) { xa = x0; xb_ = x1; nx = -1; }
                else {
                    nx = 0; xa = 0; xb_ = 0;
                    if (cx - r >= 0)            { xa  = cx - r; nx = 1; }
                    if (cx + r <= G - 1)        { if (nx) xb_ = cx + r; else xa = cx + r; nx++; }
                    if (nx == 0) continue;
                }
                // enumerate cells in this row
                if (nx < 0) {
                    const int rowc = (zz * G + yy) * G;
                    int s = g_start[sb + rowc + xa];
                    int e = g_start[sb + rowc + xb_ + 1];
                    // contiguous x-range: cells are adjacent in memory, so the
                    // point range [start(xa), start(xb+1)) is exactly the row's points
                    for (int i = s; i < e; i++) {
                        float4 p = pts[i];
                        float pn = __fadd_rn(__fadd_rn(__fmul_rn(p.x, p.x), __fmul_rn(p.y, p.y)),
                                             __fmul_rn(p.z, p.z));
                        float cr = __fmaf_rn(bz, p.z, __fmaf_rn(by, p.y, __fmul_rn(bx, p.x)));
                        float d  = __fmaf_rn(-2.0f, cr, __fadd_rn(bn, pn));
                        int   n  = __float_as_int(p.w);
                        if (d < best || (d == best && n < bi)) { best = d; bi = n; }
                    }
                } else {
                    for (int q = 0; q < nx; q++) {
                        const int xx = (q == 0) ? xa : xb_;
                        const int c = (zz * G + yy) * G + xx;
                        int s = g_start[sb + c];
                        int e = g_start[sb + c + 1];
                        for (int i = s; i < e; i++) {
                            float4 p = pts[i];
                            float pn = __fadd_rn(__fadd_rn(__fmul_rn(p.x, p.x), __fmul_rn(p.y, p.y)),
                                                 __fmul_rn(p.z, p.z));
                            float cr = __fmaf_rn(bz, p.z, __fmaf_rn(by, p.y, __fmul_rn(bx, p.x)));
                            float d  = __fmaf_rn(-2.0f, cr, __fadd_rn(bn, pn));
                            int   n  = __float_as_int(p.w);
                            if (d < best || (d == best && n < bi)) { best = d; bi = n; }
                        }
                    }
                }
            }
        }
    }

    const float* p = pc + ((size_t)b * NN + bi) * 3;
    const float dx = __fadd_rn(p[0], -bx);
    const float dy = __fadd_rn(p[1], -by);
    const float dz = __fadd_rn(p[2], -bz);
    const float ss = __fadd_rn(__fadd_rn(__fmul_rn(dx, dx), __fmul_rn(dy, dy)),
                               __fmul_rn(dz, dz));
    const float dist = sqrtf(ss);

    float* row = out_bps + (size_t)b * IN1;
    row[k]              = dist;
    row[KK + 3 * k + 0] = dx;
    row[KK + 3 * k + 1] = dy;
    row[KK + 3 * k + 2] = dz;
}

// ---- GEMM1 split-K, 2 columns per thread, f32x2 accumulators ----
// grid (H/512, INsz/CI), block 256
template <int CI>
__global__ void k_gemm1(const float* __restrict__ A,
                        const float* __restrict__ W,
                        float* __restrict__ part,
                        int INsz, int H) {
    __shared__ __align__(16) float sA[CI * 16];
    const int i0 = blockIdx.y * CI;

    for (int idx = threadIdx.x; idx < CI * 16; idx += 256) {
        const int m  = idx / CI;
        const int il = idx % CI;
        sA[il * 16 + m] = A[(size_t)m * INsz + i0 + il];
    }
    __syncthreads();

    const int j = blockIdx.x * 512 + threadIdx.x;   // col pair: j, j+256
    ull acc[16];
    #pragma unroll
    for (int m = 0; m < 16; m++) acc[m] = 0ull;

    const float* wp = W + (size_t)i0 * H + j;
    #pragma unroll 4
    for (int il = 0; il < CI; il++) {
        const float wa = wp[0];
        const float wb = wp[256];
        wp += H;
        const ull wpa = pk2(wa, wa);
        const ull wpb = pk2(wb, wb);
        const ulonglong2* ap = (const ulonglong2*)(sA + il * 16);
        ulonglong2 a0 = ap[0], a1 = ap[1], a2 = ap[2], a3 = ap[3];
        FMA2(acc[0],  a0.x, wpa, acc[0]);
        FMA2(acc[1],  a0.y, wpa, acc[1]);
        FMA2(acc[2],  a1.x, wpa, acc[2]);
        FMA2(acc[3],  a1.y, wpa, acc[3]);
        FMA2(acc[4],  a2.x, wpa, acc[4]);
        FMA2(acc[5],  a2.y, wpa, acc[5]);
        FMA2(acc[6],  a3.x, wpa, acc[6]);
        FMA2(acc[7],  a3.y, wpa, acc[7]);
        FMA2(acc[8],  a0.x, wpb, acc[8]);
        FMA2(acc[9],  a0.y, wpb, acc[9]);
        FMA2(acc[10], a1.x, wpb, acc[10]);
        FMA2(acc[11], a1.y, wpb, acc[11]);
        FMA2(acc[12], a2.x, wpb, acc[12]);
        FMA2(acc[13], a2.y, wpb, acc[13]);
        FMA2(acc[14], a3.x, wpb, acc[14]);
        FMA2(acc[15], a3.y, wpb, acc[15]);
    }

    float* pp = part + ((size_t)blockIdx.y * 16) * H + j;
    #pragma unroll
    for (int t = 0; t < 8; t++) {
        float lo, hi;
        upk2(lo, hi, acc[t]);
        pp[(size_t)(2 * t)     * H] = lo;
        pp[(size_t)(2 * t + 1) * H] = hi;
        upk2(lo, hi, acc[8 + t]);
        pp[(size_t)(2 * t)     * H + 256] = lo;
        pp[(size_t)(2 * t + 1) * H + 256] = hi;
    }
}

// ---- GEMM2: fused (reduce 32 parts of layer1 + bias + lrelu) @ W2 ----
// grid (1, H1/64), block 256; 2 cols/thread -> H2=512
__global__ void k_gemm2f(const float* __restrict__ part1,
                         const float* __restrict__ b1v,
                         const float* __restrict__ W2,
                         float* __restrict__ part2) {
    __shared__ __align__(16) float sA[64 * 16];
    const int i0 = blockIdx.y * 64;

    for (int idx = threadIdx.x; idx < 64 * 16; idx += 256) {
        const int m  = idx / 64;
        const int il = idx % 64;
        float s = 0.0f;
        #pragma unroll
        for (int q = 0; q < 32; q++)
            s += part1[(size_t)(q * 16 + m) * H1 + i0 + il];
        s += b1v[i0 + il];
        if (s < 0.0f) s *= 0.2f;
        sA[il * 16 + m] = s;
    }
    __syncthreads();

    const int j = threadIdx.x;
    ull acc[16];
    #pragma unroll
    for (int m = 0; m < 16; m++) acc[m] = 0ull;

    const float* wp = W2 + (size_t)i0 * H2 + j;
    #pragma unroll 4
    for (int il = 0; il < 64; il++) {
        const float wa = wp[0];
        const float wb = wp[256];
        wp += H2;
        const ull wpa = pk2(wa, wa);
        const ull wpb = pk2(wb, wb);
        const ulonglong2* ap = (const ulonglong2*)(sA + il * 16);
        ulonglong2 a0 = ap[0], a1 = ap[1], a2 = ap[2], a3 = ap[3];
        FMA2(acc[0],  a0.x, wpa, acc[0]);
        FMA2(acc[1],  a0.y, wpa, acc[1]);
        FMA2(acc[2],  a1.x, wpa, acc[2]);
        FMA2(acc[3],  a1.y, wpa, acc[3]);
        FMA2(acc[4],  a2.x, wpa, acc[4]);
        FMA2(acc[5],  a2.y, wpa, acc[5]);
        FMA2(acc[6],  a3.x, wpa, acc[6]);
        FMA2(acc[7],  a3.y, wpa, acc[7]);
        FMA2(acc[8],  a0.x, wpb, acc[8]);
        FMA2(acc[9],  a0.y, wpb, acc[9]);
        FMA2(acc[10], a1.x, wpb, acc[10]);
        FMA2(acc[11], a1.y, wpb, acc[11]);
        FMA2(acc[12], a2.x, wpb, acc[12]);
        FMA2(acc[13], a2.y, wpb, acc[13]);
        FMA2(acc[14], a3.x, wpb, acc[14]);
        FMA2(acc[15], a3.y, wpb, acc[15]);
    }

    float* pp = part2 + ((size_t)blockIdx.y * 16) * H2 + j;
    #pragma unroll
    for (int t = 0; t < 8; t++) {
        float lo, hi;
        upk2(lo, hi, acc[t]);
        pp[(size_t)(2 * t)     * H2] = lo;
        pp[(size_t)(2 * t + 1) * H2] = hi;
        upk2(lo, hi, acc[8 + t]);
        pp[(size_t)(2 * t)     * H2 + 256] = lo;
        pp[(size_t)(2 * t + 1) * H2 + 256] = hi;
    }
}

// ---- GEMM3: fused (reduce 16 parts of layer2 + bias + lrelu) @ W3 ----
// grid (1, H2/32), block 256; 1 col/thread -> OUTD=256
__global__ void k_gemm3f(const float* __restrict__ part2,
                         const float* __restrict__ b2v,
                         const float* __restrict__ W3,
                         float* __restrict__ part3) {
    __shared__ __align__(16) float sA[32 * 16];
    const int i0 = blockIdx.y * 32;

    for (int idx = threadIdx.x; idx < 32 * 16; idx += 256) {
        const int m  = idx / 32;
        const int il = idx % 32;
        float s = 0.0f;
        #pragma unroll
        for (int q = 0; q < 16; q++)
            s += part2[(size_t)(q * 16 + m) * H2 + i0 + il];
        s += b2v[i0 + il];
        if (s < 0.0f) s *= 0.2f;
        sA[il * 16 + m] = s;
    }
    __syncthreads();

    const int j = threadIdx.x;
    ull acc[8];
    #pragma unroll
    for (int m = 0; m < 8; m++) acc[m] = 0ull;

    const float* wp = W3 + (size_t)i0 * OUTD + j;
    #pragma unroll 4
    for (int il = 0; il < 32; il++) {
        const float w = *wp;
        wp += OUTD;
        const ull wpk = pk2(w, w);
        const ulonglong2* ap = (const ulonglong2*)(sA + il * 16);
        ulonglong2 a0 = ap[0], a1 = ap[1], a2 = ap[2], a3 = ap[3];
        FMA2(acc[0], a0.x, wpk, acc[0]);
        FMA2(acc[1], a0.y, wpk, acc[1]);
        FMA2(acc[2], a1.x, wpk, acc[2]);
        FMA2(acc[3], a1.y, wpk, acc[3]);
        FMA2(acc[4], a2.x, wpk, acc[4]);
        FMA2(acc[5], a2.y, wpk, acc[5]);
        FMA2(acc[6], a3.x, wpk, acc[6]);
        FMA2(acc[7], a3.y, wpk, acc[7]);
    }

    float* pp = part3 + ((size_t)blockIdx.y * 16) * OUTD + j;
    #pragma unroll
    for (int t = 0; t < 8; t++) {
        float lo, hi;
        upk2(lo, hi, acc[t]);
        pp[(size_t)(2 * t)     * OUTD] = lo;
        pp[(size_t)(2 * t + 1) * OUTD] = hi;
    }
}

// ---- final: reduce 16 parts of layer3 + bias ----
__global__ void k_final(const float* __restrict__ part3,
                        const float* __restrict__ b3v,
                        float* __restrict__ outv) {
    const int t = blockIdx.x * 256 + threadIdx.x;    // over BB*OUTD
    const int m = t >> 8;
    const int j = t & 255;
    float s = 0.0f;
    #pragma unroll
    for (int q = 0; q < 16; q++)
        s += part3[(size_t)(q * 16 + m) * OUTD + j];
    s += b3v[j];
    outv[t] = s;
}

// ============================================================
extern "C" void kernel_launch(void* const* d_in, const int* in_sizes, int n_in,
                              void* d_out, int out_size) {
    const float* pc    = (const float*)d_in[0];
    const float* basis = (const float*)d_in[1];
    const float* W1    = (const float*)d_in[2];
    const float* b1    = (const float*)d_in[3];
    const float* W2    = (const float*)d_in[4];
    const float* b2    = (const float*)d_in[5];
    const float* W3    = (const float*)d_in[6];
    const float* b3    = (const float*)d_in[7];

    float* out = (float*)d_out;            // global_feature: [16][256]
    float* bps = out + BB * OUTD;          // bps_feature:    [16][16384]

    void *cnt;
    float *p1, *p2, *p3;
    cudaGetSymbolAddress(&cnt, g_count);
    cudaGetSymbolAddress((void**)&p1, g_part1);
    cudaGetSymbolAddress((void**)&p2, g_part2);
    cudaGetSymbolAddress((void**)&p3, g_part3);

    cudaMemsetAsync(cnt, 0, BB * NCELLS * sizeof(int));
    k_count  <<<BB * NN / 256, 256>>>(pc);
    k_scan   <<<BB, 1024>>>();
    k_scatter<<<BB * NN / 256, 256>>>(pc);
    k_query  <<<BB * KK / 256, 256>>>(pc, basis, bps);

    k_gemm1<512><<<dim3(H1 / 512, IN1 / 512), 256>>>(bps, W1, p1, IN1, H1);
    k_gemm2f<<<dim3(1, H1 / 64), 256>>>(p1, b1, W2, p2);
    k_gemm3f<<<dim3(1, H2 / 32), 256>>>(p2, b2, W3, p3);
    k_final <<<BB * OUTD / 256, 256>>>(p3, b3, out);
}

// round 5
// speedup vs baseline: 1.8944x; 1.8944x over previous
#include <cuda_runtime.h>
#include <math.h>
#include <float.h>

#define BB   16
#define NN   4096
#define KK   4096
#define NCHUNK 4
#define CHUNK  1024      // NN / NCHUNK
#define IN1  16384
#define H1   1024
#define H2   512
#define OUTD 256

typedef unsigned long long ull;

#define FMA2(out, a, b, c) asm("fma.rn.f32x2 %0, %1, %2, %3;" : "=l"(out) : "l"(a), "l"(b), "l"(c))
#define MUL2(out, a, b)    asm("mul.rn.f32x2 %0, %1, %2;"     : "=l"(out) : "l"(a), "l"(b))
#define ADD2(out, a, b)    asm("add.rn.f32x2 %0, %1, %2;"     : "=l"(out) : "l"(a), "l"(b))

__device__ __forceinline__ ull pk2(float lo, float hi) {
    ull r; asm("mov.b64 %0, {%1, %2};" : "=l"(r) : "f"(lo), "f"(hi)); return r;
}
__device__ __forceinline__ void upk2(float& lo, float& hi, ull v) {
    asm("mov.b64 {%0, %1}, %2;" : "=f"(lo), "=f"(hi) : "l"(v));
}

// ---- scratch ----
__device__ float g_best[BB * KK * NCHUNK];
__device__ int   g_bidx[BB * KK * NCHUNK];
__device__ float g_part1[128 * BB * H1];      // 8 MB
__device__ float g_h1[BB * H1];
__device__ float g_part2[64 * BB * H2];       // 2 MB
__device__ float g_h2[BB * H2];
__device__ float g_part3[16 * BB * OUTD];

// ============================================================
// Kernel 1: partial argmin over an N-chunk, bit-exact reference
// arithmetic (validated in R3), 2 points per f32x2 op, deferred
// within-pair index resolution => 11 warp-inst/pair inner loop.
//   spA[i] = {-2x(2i), -2x(2i+1), -2y(2i), -2y(2i+1)}
//   spB[i] = {-2z(2i), -2z(2i+1),  pn(2i),  pn(2i+1)}
//   c3 = fma(bz,-2z, fma(by,-2y, rn(bx*-2x))) == -2*cr exactly
//   d  = rn(c3 + rn(bn+pn)) == reference fma(-2,cr,bn+pn)
// grid: (KK/256, NCHUNK, BB), block 256
// ============================================================
__global__ void k_argmin(const float* __restrict__ pc,
                         const float* __restrict__ basis) {
    __shared__ __align__(16) ulonglong2 spA[CHUNK / 2];
    __shared__ __align__(16) ulonglong2 spB[CHUNK / 2];
    const int b  = blockIdx.z;
    const int c  = blockIdx.y;
    const int n0 = c * CHUNK;

    const float* pcb = pc + ((size_t)b * NN + n0) * 3;
    for (int i = threadIdx.x; i < CHUNK / 2; i += blockDim.x) {
        float x0 = pcb[6 * i + 0], y0 = pcb[6 * i + 1], z0 = pcb[6 * i + 2];
        float x1 = pcb[6 * i + 3], y1 = pcb[6 * i + 4], z1 = pcb[6 * i + 5];
        float pn0 = __fadd_rn(__fadd_rn(__fmul_rn(x0, x0), __fmul_rn(y0, y0)),
                              __fmul_rn(z0, z0));
        float pn1 = __fadd_rn(__fadd_rn(__fmul_rn(x1, x1), __fmul_rn(y1, y1)),
                              __fmul_rn(z1, z1));
        ((float4*)spA)[i] = make_float4(-2.0f * x0, -2.0f * x1, -2.0f * y0, -2.0f * y1);
        ((float4*)spB)[i] = make_float4(-2.0f * z0, -2.0f * z1, pn0, pn1);
    }
    __syncthreads();

    const int k = blockIdx.x * blockDim.x + threadIdx.x;
    const float bx = basis[k * 3 + 0];
    const float by = basis[k * 3 + 1];
    const float bz = basis[k * 3 + 2];
    const float bn = __fadd_rn(__fadd_rn(__fmul_rn(bx, bx), __fmul_rn(by, by)),
                               __fmul_rn(bz, bz));
    const ull bxp = pk2(bx, bx);
    const ull byp = pk2(by, by);
    const ull bzp = pk2(bz, bz);
    const ull bnp = pk2(bn, bn);

    float best = FLT_MAX;
    int   bp   = 0;                       // winning PAIR index
    #pragma unroll 8
    for (int i = 0; i < CHUNK / 2; i++) {
        ulonglong2 qa = spA[i];
        ulonglong2 qb = spB[i];
        ull cr, t, d;
        MUL2(cr, bxp, qa.x);
        FMA2(cr, byp, qa.y, cr);
        FMA2(cr, bzp, qb.x, cr);
        ADD2(t, bnp, qb.y);
        ADD2(d, cr, t);
        float d0, d1;
        upk2(d0, d1, d);
        float pm = fminf(d0, d1);
        bp   = (pm < best) ? i : bp;      // strict < => earlier pair on tie
        best = fminf(best, pm);
    }

    // resolve even/odd inside the winning pair (tie -> even = lower n)
    {
        ulonglong2 qa = spA[bp];
        ulonglong2 qb = spB[bp];
        float m2x0, m2x1, m2y0, m2y1, m2z0, m2z1, pn0, pn1;
        upk2(m2x0, m2x1, qa.x);
        upk2(m2y0, m2y1, qa.y);
        upk2(m2z0, m2z1, qb.x);
        upk2(pn0,  pn1,  qb.y);
        float c0 = __fmaf_rn(bz, m2z0, __fmaf_rn(by, m2y0, __fmul_rn(bx, m2x0)));
        float d0 = __fadd_rn(c0, __fadd_rn(bn, pn0));
        float c1 = __fmaf_rn(bz, m2z1, __fmaf_rn(by, m2y1, __fmul_rn(bx, m2x1)));
        float d1 = __fadd_rn(c1, __fadd_rn(bn, pn1));
        int bi = 2 * bp + ((d0 <= d1) ? 0 : 1);

        const int o = (b * KK + k) * NCHUNK + c;
        g_best[o] = best;
        g_bidx[o] = n0 + bi;
    }
}

// ============================================================
// Kernel 2: combine chunk partials (ascending order, strict <),
// gather nearest point, write bps row: [dists(4096) | deltas(3*4096)]
// ============================================================
__global__ void k_finish(const float* __restrict__ pc,
                         const float* __restrict__ basis,
                         float* __restrict__ out_bps) {
    const int t = blockIdx.x * blockDim.x + threadIdx.x;
    if (t >= BB * KK) return;
    const int b = t >> 12;
    const int k = t & (KK - 1);

    float best = g_best[t * NCHUNK];
    int   bi   = g_bidx[t * NCHUNK];
    #pragma unroll
    for (int c = 1; c < NCHUNK; c++) {
        float v = g_best[t * NCHUNK + c];
        int   i = g_bidx[t * NCHUNK + c];
        if (v < best) { best = v; bi = i; }
    }

    const float* p = pc + ((size_t)b * NN + bi) * 3;
    const float dx = __fadd_rn(p[0], -basis[k * 3 + 0]);
    const float dy = __fadd_rn(p[1], -basis[k * 3 + 1]);
    const float dz = __fadd_rn(p[2], -basis[k * 3 + 2]);
    const float ss = __fadd_rn(__fadd_rn(__fmul_rn(dx, dx), __fmul_rn(dy, dy)),
                               __fmul_rn(dz, dz));
    const float dist = sqrtf(ss);

    float* row = out_bps + (size_t)b * IN1;
    row[k]              = dist;
    row[KK + 3 * k + 0] = dx;
    row[KK + 3 * k + 1] = dy;
    row[KK + 3 * k + 2] = dz;
}

// ============================================================
// Split-K GEMM, 2 cols/thread, f32x2 acc.
// grid (H/512, INsz/CI), block 256. part[ic][m][j].
// ============================================================
template <int CI>
__global__ void k_gemm2c(const float* __restrict__ A,
                         const float* __restrict__ W,
                         float* __restrict__ part,
                         int INsz, int H) {
    __shared__ __align__(16) float sA[CI * 16];
    const int i0 = blockIdx.y * CI;

    for (int idx = threadIdx.x; idx < CI * 16; idx += 256) {
        const int m  = idx / CI;
        const int il = idx % CI;
        sA[il * 16 + m] = A[(size_t)m * INsz + i0 + il];
    }
    __syncthreads();

    const int j = blockIdx.x * 512 + threadIdx.x;   // cols j and j+256
    ull acc[16];
    #pragma unroll
    for (int m = 0; m < 16; m++) acc[m] = 0ull;

    const float* wp = W + (size_t)i0 * H + j;
    #pragma unroll 4
    for (int il = 0; il < CI; il++) {
        const float wa = wp[0];
        const float wb = wp[256];
        wp += H;
        const ull wpa = pk2(wa, wa);
        const ull wpb = pk2(wb, wb);
        const ulonglong2* ap = (const ulonglong2*)(sA + il * 16);
        ulonglong2 a0 = ap[0], a1 = ap[1], a2 = ap[2], a3 = ap[3];
        FMA2(acc[0],  a0.x, wpa, acc[0]);
        FMA2(acc[1],  a0.y, wpa, acc[1]);
        FMA2(acc[2],  a1.x, wpa, acc[2]);
        FMA2(acc[3],  a1.y, wpa, acc[3]);
        FMA2(acc[4],  a2.x, wpa, acc[4]);
        FMA2(acc[5],  a2.y, wpa, acc[5]);
        FMA2(acc[6],  a3.x, wpa, acc[6]);
        FMA2(acc[7],  a3.y, wpa, acc[7]);
        FMA2(acc[8],  a0.x, wpb, acc[8]);
        FMA2(acc[9],  a0.y, wpb, acc[9]);
        FMA2(acc[10], a1.x, wpb, acc[10]);
        FMA2(acc[11], a1.y, wpb, acc[11]);
        FMA2(acc[12], a2.x, wpb, acc[12]);
        FMA2(acc[13], a2.y, wpb, acc[13]);
        FMA2(acc[14], a3.x, wpb, acc[14]);
        FMA2(acc[15], a3.y, wpb, acc[15]);
    }

    float* pp = part + ((size_t)blockIdx.y * 16) * H + j;
    #pragma unroll
    for (int t = 0; t < 8; t++) {
        float lo, hi;
        upk2(lo, hi, acc[t]);
        pp[(size_t)(2 * t)     * H] = lo;
        pp[(size_t)(2 * t + 1) * H] = hi;
        upk2(lo, hi, acc[8 + t]);
        pp[(size_t)(2 * t)     * H + 256] = lo;
        pp[(size_t)(2 * t + 1) * H + 256] = hi;
    }
}

// ============================================================
// Split-K GEMM, 1 col/thread (for H=256 tail layer).
// grid (H/256, INsz/CI), block 256.
// ============================================================
template <int CI>
__global__ void k_gemm1c(const float* __restrict__ A,
                         const float* __restrict__ W,
                         float* __restrict__ part,
                         int INsz, int H) {
    __shared__ __align__(16) float sA[CI * 16];
    const int i0 = blockIdx.y * CI;

    for (int idx = threadIdx.x; idx < CI * 16; idx += 256) {
        const int m  = idx / CI;
        const int il = idx % CI;
        sA[il * 16 + m] = A[(size_t)m * INsz + i0 + il];
    }
    __syncthreads();

    const int j = blockIdx.x * 256 + threadIdx.x;
    ull acc[8];
    #pragma unroll
    for (int m = 0; m < 8; m++) acc[m] = 0ull;

    const float* wp = W + (size_t)i0 * H + j;
    #pragma unroll 4
    for (int il = 0; il < CI; il++) {
        const float w = *wp;
        wp += H;
        const ull wpk = pk2(w, w);
        const ulonglong2* ap = (const ulonglong2*)(sA + il * 16);
        ulonglong2 a0 = ap[0], a1 = ap[1], a2 = ap[2], a3 = ap[3];
        FMA2(acc[0], a0.x, wpk, acc[0]);
        FMA2(acc[1], a0.y, wpk, acc[1]);
        FMA2(acc[2], a1.x, wpk, acc[2]);
        FMA2(acc[3], a1.y, wpk, acc[3]);
        FMA2(acc[4], a2.x, wpk, acc[4]);
        FMA2(acc[5], a2.y, wpk, acc[5]);
        FMA2(acc[6], a3.x, wpk, acc[6]);
        FMA2(acc[7], a3.y, wpk, acc[7]);
    }

    float* pp = part + ((size_t)blockIdx.y * 16) * H + j;
    #pragma unroll
    for (int t = 0; t < 8; t++) {
        float lo, hi;
        upk2(lo, hi, acc[t]);
        pp[(size_t)(2 * t)     * H] = lo;
        pp[(size_t)(2 * t + 1) * H] = hi;
    }
}

// ============================================================
// Deterministic split-K reduce + bias (+ optional leaky relu).
// One thread per output element; nparts independent strided loads.
// ============================================================
__global__ void k_reduce(const float* __restrict__ part,
                         const float* __restrict__ bias,
                         float* __restrict__ outv,
                         int H, int nparts, int do_lrelu) {
    const int t = blockIdx.x * blockDim.x + threadIdx.x;
    const int total = BB * H;
    if (t >= total) return;
    float s = 0.0f;
    #pragma unroll 8
    for (int p = 0; p < nparts; p++) s += part[(size_t)p * total + t];
    s += bias[t & (H - 1)];
    if (do_lrelu && s < 0.0f) s *= 0.2f;
    outv[t] = s;
}

// ============================================================
extern "C" void kernel_launch(void* const* d_in, const int* in_sizes, int n_in,
                              void* d_out, int out_size) {
    const float* pc    = (const float*)d_in[0];
    const float* basis = (const float*)d_in[1];
    const float* W1    = (const float*)d_in[2];
    const float* b1    = (const float*)d_in[3];
    const float* W2    = (const float*)d_in[4];
    const float* b2    = (const float*)d_in[5];
    const float* W3    = (const float*)d_in[6];
    const float* b3    = (const float*)d_in[7];

    float* out = (float*)d_out;            // global_feature: [16][256]
    float* bps = out + BB * OUTD;          // bps_feature:    [16][16384]

    float *p1, *p2, *p3, *h1, *h2;
    cudaGetSymbolAddress((void**)&p1, g_part1);
    cudaGetSymbolAddress((void**)&p2, g_part2);
    cudaGetSymbolAddress((void**)&p3, g_part3);
    cudaGetSymbolAddress((void**)&h1, g_h1);
    cudaGetSymbolAddress((void**)&h2, g_h2);

    k_argmin<<<dim3(KK / 256, NCHUNK, BB), 256>>>(pc, basis);
    k_finish<<<(BB * KK) / 256, 256>>>(pc, basis, bps);

    // layer 1: [16,16384] @ [16384,1024] — 256 blocks, 128-way split-K
    k_gemm2c<128><<<dim3(H1 / 512, IN1 / 128), 256>>>(bps, W1, p1, IN1, H1);
    k_reduce<<<(BB * H1) / 256, 256>>>(p1, b1, h1, H1, 128, 1);

    // layer 2: [16,1024] @ [1024,512] — 64 blocks, 64-way split-K
    k_gemm2c<16><<<dim3(H2 / 512, H1 / 16), 256>>>(h1, W2, p2, H1, H2);
    k_reduce<<<(BB * H2) / 256, 256>>>(p2, b2, h2, H2, 64, 1);

    // layer 3: [16,512] @ [512,256] — 16 blocks, 16-way split-K
    k_gemm1c<32><<<dim3(OUTD / 256, H2 / 32), 256>>>(h2, W3, p3, H2, OUTD);
    k_reduce<<<(BB * OUTD) / 256, 256>>>(p3, b3, out, OUTD, 16, 0);
}